// round 6
// baseline (speedup 1.0000x reference)
#include <cuda_runtime.h>
#include <cuda_fp16.h>
#include <cstdint>
#include <cstddef>

// ---------------- problem constants ----------------
#define TT   16384      // tokens = 4*4096
#define DIN  1280
#define DOUT 3840
#define KK   1408       // 1280 (x) + 16 (shared) + 96 (routed) + 16 pad
#define HC   128        // H columns: 16 shared | 96 routed | 6 router | 10 pad

// ---------------- device scratch (no cudaMalloc allowed) ----------------
__device__ __align__(256) __half g_Ah[(size_t)TT * KK];
__device__ __align__(256) __half g_Al[(size_t)TT * KK];
__device__ __align__(256) __half g_B [(size_t)DOUT * KK];
__device__ __align__(256) __half g_W1[HC * DIN];
__device__ __align__(256) float  g_H1[(size_t)TT * HC];
__device__ __align__(256) float  g_H2[(size_t)TT * HC];

// ---------------- helpers ----------------
__device__ __forceinline__ uint32_t s2u(const void* p) {
    return (uint32_t)__cvta_generic_to_shared(p);
}
__device__ __forceinline__ uint32_t swz(uint32_t o) { return o ^ ((o >> 3) & 0x70); }

__device__ __forceinline__ void cpa16(uint32_t dst, const void* src) {
    asm volatile("cp.async.cg.shared.global [%0], [%1], 16;\n" :: "r"(dst), "l"(src) : "memory");
}
__device__ __forceinline__ void cp_commit() {
    asm volatile("cp.async.commit_group;\n" ::: "memory");
}

__device__ __forceinline__ void ldsm4(uint32_t* r, uint32_t addr) {
    asm volatile("ldmatrix.sync.aligned.m8n8.x4.shared.b16 {%0,%1,%2,%3}, [%4];"
                 : "=r"(r[0]), "=r"(r[1]), "=r"(r[2]), "=r"(r[3]) : "r"(addr));
}

__device__ __forceinline__ void mma16816(float* c, const uint32_t* a, uint32_t b0, uint32_t b1) {
    asm volatile(
        "mma.sync.aligned.m16n8k16.row.col.f32.f16.f16.f32 "
        "{%0,%1,%2,%3}, {%4,%5,%6,%7}, {%8,%9}, {%0,%1,%2,%3};"
        : "+f"(c[0]), "+f"(c[1]), "+f"(c[2]), "+f"(c[3])
        : "r"(a[0]), "r"(a[1]), "r"(a[2]), "r"(a[3]), "r"(b0), "r"(b1));
}

__device__ __forceinline__ void split2(float v, __half& h, __half& l) {
    h = __float2half(v);
    l = __float2half(v - __half2float(h));
}

// ---------------- prep kernels ----------------
__global__ void prep_B(const float* __restrict__ base_w,
                       const float* __restrict__ sw2,
                       const float* __restrict__ rw2) {
    __shared__ float tile[32][33];
    const int kt = blockIdx.x * 32;
    const int nt = blockIdx.y * 32;
    const int tx = threadIdx.x, ty = threadIdx.y;  // (32, 8)
    #pragma unroll
    for (int j = 0; j < 4; j++) {
        int k = kt + ty + j * 8;
        int n = nt + tx;
        float v;
        if (k < 1280)       v = base_w[(size_t)k * DOUT + n];
        else if (k < 1296)  v = sw2[(size_t)(k - 1280) * DOUT + n];
        else if (k < 1392)  v = rw2[(size_t)(k - 1296) * DOUT + n];
        else                v = 0.f;
        tile[ty + j * 8][tx] = v;
    }
    __syncthreads();
    #pragma unroll
    for (int j = 0; j < 4; j++) {
        int n = nt + ty + j * 8;
        int k = kt + tx;
        g_B[(size_t)n * KK + k] = __float2half(tile[tx][ty + j * 8]);
    }
}

__global__ void prep_W1(const float* __restrict__ sw1,
                        const float* __restrict__ rw1,
                        const float* __restrict__ rtw) {
    int idx = blockIdx.x * blockDim.x + threadIdx.x;
    if (idx >= HC * DIN) return;
    int n = idx / DIN;
    int k = idx - n * DIN;
    float v;
    if (n < 16)        v = sw1[(size_t)k * 16 + n];
    else if (n < 112)  { int jr = n - 16; int e = jr >> 4; int r = jr & 15;
                         v = rw1[((size_t)e * DIN + k) * 16 + r]; }
    else if (n < 118)  v = rtw[(size_t)k * 6 + (n - 112)];
    else               v = 0.f;
    g_W1[idx] = __float2half(v);
}

__global__ void split_x(const float* __restrict__ x) {
    int idx = blockIdx.x * blockDim.x + threadIdx.x;
    if (idx >= TT * DIN) return;
    int t = idx / DIN;
    int k = idx - t * DIN;
    __half h, l; split2(x[idx], h, l);
    size_t o = (size_t)t * KK + k;
    g_Ah[o] = h; g_Al[o] = l;
}

__global__ void gate_kernel(const float* __restrict__ router_b) {
    int t = blockIdx.x * blockDim.x + threadIdx.x;
    if (t >= TT) return;
    const float* h1 = g_H1 + (size_t)t * HC;
    const float* h2 = g_H2 + (size_t)t * HC;
    float h[118];
    #pragma unroll
    for (int j = 0; j < 118; j++) h[j] = h1[j] + h2[j];
    float gates[6];
    float mx = -1e30f;
    #pragma unroll
    for (int e = 0; e < 6; e++) { gates[e] = h[112 + e] + router_b[e]; mx = fmaxf(mx, gates[e]); }
    float s = 0.f;
    #pragma unroll
    for (int e = 0; e < 6; e++) { gates[e] = expf(gates[e] - mx); s += gates[e]; }
    float inv = 1.f / s;
    #pragma unroll
    for (int e = 0; e < 6; e++) gates[e] *= inv;
    float cw[6] = {0.f, 0.f, 0.f, 0.f, 0.f, 0.f};
    bool used[6] = {false, false, false, false, false, false};
    for (int k = 0; k < 3; k++) {
        int bi = 0; float bv = -1.f;
        #pragma unroll
        for (int e = 0; e < 6; e++)
            if (!used[e] && gates[e] > bv) { bv = gates[e]; bi = e; }
        used[bi] = true; cw[bi] = bv;
    }
    size_t base = (size_t)t * KK + 1280;
    #pragma unroll
    for (int j = 0; j < 16; j++)
        g_Ah[base + j] = __float2half(h[j]);
    #pragma unroll
    for (int e = 0; e < 6; e++) {
        float w = cw[e];
        #pragma unroll
        for (int r = 0; r < 16; r++)
            g_Ah[base + 16 + e * 16 + r] = __float2half(w * h[16 + e * 16 + r]);
    }
    #pragma unroll
    for (int j = 112; j < 128; j++)
        g_Ah[base + j] = __float2half(0.f);
}

// ---------------- GEMM1: fp16x2 (Ah+Al) @ W1, split-K=2 ----------------
// BM=128, BN=128, BK=64, KT=10 per half. blockIdx.x = K-half.
// Stage: Ah @0, Al @16K, B @32K; stride 48K, 2 stages. 2 CTAs/SM.
__global__ __launch_bounds__(256, 2)
void gemm1_k() {
    constexpr int KT = 10;
    extern __shared__ __align__(1024) char smem[];
    const uint32_t sb = s2u(smem);
    const int tid = threadIdx.x;
    const int wid = tid >> 5;
    const int lane = tid & 31;
    const int m0 = blockIdx.y * 128;
    const int kbase = blockIdx.x * 640;          // K half offset
    float* Hout = blockIdx.x ? g_H2 : g_H1;

    const int wr = wid >> 2;
    const int wc = wid & 3;
    const int m_warp = wr * 64;
    const int n_warp = wc * 32;
    const int lm_row = lane & 15;
    const int lm_kg  = lane >> 4;

    auto load_tile = [&](int s, int it) {
        const int k0 = kbase + it * 64;
        const uint32_t st = sb + (uint32_t)s * 49152u;
        #pragma unroll
        for (int r = 0; r < 4; r++) {
            int c = tid + r * 256;
            int row = c >> 3, ch = c & 7;
            uint32_t d = swz((uint32_t)(row * 128 + ch * 16));
            size_t go = (size_t)(m0 + row) * KK + k0 + ch * 8;
            cpa16(st + d,          g_Ah + go);
            cpa16(st + 16384 + d,  g_Al + go);
        }
        #pragma unroll
        for (int r = 0; r < 4; r++) {
            int c = tid + r * 256;
            int row = c >> 3, ch = c & 7;
            uint32_t d = swz((uint32_t)(row * 128 + ch * 16));
            size_t go = (size_t)row * DIN + k0 + ch * 8;
            cpa16(st + 32768 + d,  g_W1 + go);
        }
        cp_commit();
    };

    float acc[4][4][4];
    #pragma unroll
    for (int a = 0; a < 4; a++)
        #pragma unroll
        for (int b = 0; b < 4; b++)
            #pragma unroll
            for (int c = 0; c < 4; c++) acc[a][b][c] = 0.f;

    load_tile(0, 0);

    for (int i = 0; i < KT; i++) {
        const int buf = i & 1;
        if (i + 1 < KT) {
            load_tile(buf ^ 1, i + 1);
            asm volatile("cp.async.wait_group 1;" ::: "memory");
        } else {
            asm volatile("cp.async.wait_group 0;" ::: "memory");
        }
        __syncthreads();

        const uint32_t st = sb + (uint32_t)buf * 49152u;
        #pragma unroll
        for (int ks = 0; ks < 4; ks++) {
            const int kg = ks * 2 + lm_kg;
            uint32_t bb[2][4];
            #pragma unroll
            for (int nh = 0; nh < 2; nh++) {
                uint32_t off = swz((uint32_t)((n_warp + nh * 16 + lm_row) * 128 + kg * 16));
                ldsm4(bb[nh], st + 32768 + off);
            }
            #pragma unroll
            for (int mh = 0; mh < 2; mh++) {
                uint32_t ah[2][4], al[2][4];
                #pragma unroll
                for (int q = 0; q < 2; q++) {
                    int mt = mh * 2 + q;
                    uint32_t off = swz((uint32_t)((m_warp + mt * 16 + lm_row) * 128 + kg * 16));
                    ldsm4(ah[q], st + off);
                    ldsm4(al[q], st + 16384 + off);
                }
                #pragma unroll
                for (int q = 0; q < 2; q++)
                    #pragma unroll
                    for (int nt = 0; nt < 4; nt++) {
                        const int nh = nt >> 1, sub = nt & 1;
                        mma16816(acc[mh * 2 + q][nt], ah[q], bb[nh][sub], bb[nh][sub + 2]);
                    }
                #pragma unroll
                for (int q = 0; q < 2; q++)
                    #pragma unroll
                    for (int nt = 0; nt < 4; nt++) {
                        const int nh = nt >> 1, sub = nt & 1;
                        mma16816(acc[mh * 2 + q][nt], al[q], bb[nh][sub], bb[nh][sub + 2]);
                    }
            }
        }
        __syncthreads();
    }

    const int g  = lane >> 2;
    const int tg = lane & 3;
    #pragma unroll
    for (int mt = 0; mt < 4; mt++) {
        #pragma unroll
        for (int nt = 0; nt < 4; nt++) {
            int n = n_warp + nt * 8 + tg * 2;
            #pragma unroll
            for (int half = 0; half < 2; half++) {
                int m = m0 + m_warp + mt * 16 + g + half * 8;
                float2 v;
                v.x = acc[mt][nt][half * 2 + 0];
                v.y = acc[mt][nt][half * 2 + 1];
                *reinterpret_cast<float2*>(Hout + (size_t)m * HC + n) = v;
            }
        }
    }
}

// ---------------- GEMM2: 1-term fp16, BM=256, BN=128, BK=64, 512 thr, 3-stage ----------------
// Stage layout: Ah @0 (32KB), B @32K (16KB); stage stride 48K. 3 stages = 144KB.
__global__ __launch_bounds__(512, 1)
void gemm2_k(const float* __restrict__ bias, float* __restrict__ Cout) {
    constexpr int KT = 22;
    extern __shared__ __align__(1024) char smem[];
    const uint32_t sb = s2u(smem);
    const int tid = threadIdx.x;
    const int wid = tid >> 5;
    const int lane = tid & 31;
    const int m0 = blockIdx.y * 256;
    const int n0 = blockIdx.x * 128;

    const int wr = wid >> 2;          // 0-3 -> m_warp 64*wr
    const int wc = wid & 3;           // 0-3 -> n_warp 32*wc
    const int m_warp = wr * 64;
    const int n_warp = wc * 32;
    const int lm_row = lane & 15;
    const int lm_kg  = lane >> 4;

    auto load_tile = [&](int s, int it) {
        const int k0 = it * 64;
        const uint32_t st = sb + (uint32_t)s * 49152u;
        // A: 256 rows x 8 chunks = 2048
        #pragma unroll
        for (int r = 0; r < 4; r++) {
            int c = tid + r * 512;
            int row = c >> 3, ch = c & 7;
            uint32_t d = swz((uint32_t)(row * 128 + ch * 16));
            cpa16(st + d, g_Ah + (size_t)(m0 + row) * KK + k0 + ch * 8);
        }
        // B: 128 rows x 8 chunks = 1024
        #pragma unroll
        for (int r = 0; r < 2; r++) {
            int c = tid + r * 512;
            int row = c >> 3, ch = c & 7;
            uint32_t d = swz((uint32_t)(row * 128 + ch * 16));
            cpa16(st + 32768 + d, g_B + (size_t)(n0 + row) * KK + k0 + ch * 8);
        }
        cp_commit();
    };

    float acc[4][4][4];
    #pragma unroll
    for (int a = 0; a < 4; a++)
        #pragma unroll
        for (int b = 0; b < 4; b++)
            #pragma unroll
            for (int c = 0; c < 4; c++) acc[a][b][c] = 0.f;

    load_tile(0, 0);
    load_tile(1, 1);

    for (int i = 0; i < KT; i++) {
        const int buf = i % 3;
        if (i + 2 < KT) {
            load_tile((i + 2) % 3, i + 2);
            asm volatile("cp.async.wait_group 2;" ::: "memory");
        } else if (i + 1 < KT) {
            asm volatile("cp.async.wait_group 1;" ::: "memory");
        } else {
            asm volatile("cp.async.wait_group 0;" ::: "memory");
        }
        __syncthreads();

        const uint32_t st = sb + (uint32_t)buf * 49152u;
        #pragma unroll
        for (int ks = 0; ks < 4; ks++) {
            const int kg = ks * 2 + lm_kg;
            uint32_t bb[2][4];
            #pragma unroll
            for (int nh = 0; nh < 2; nh++) {
                uint32_t off = swz((uint32_t)((n_warp + nh * 16 + lm_row) * 128 + kg * 16));
                ldsm4(bb[nh], st + 32768 + off);
            }
            uint32_t ah[4][4];
            #pragma unroll
            for (int mt = 0; mt < 4; mt++) {
                uint32_t off = swz((uint32_t)((m_warp + mt * 16 + lm_row) * 128 + kg * 16));
                ldsm4(ah[mt], st + off);
            }
            #pragma unroll
            for (int mt = 0; mt < 4; mt++)
                #pragma unroll
                for (int nt = 0; nt < 4; nt++) {
                    const int nh = nt >> 1, sub = nt & 1;
                    mma16816(acc[mt][nt], ah[mt], bb[nh][sub], bb[nh][sub + 2]);
                }
        }
        __syncthreads();
    }

    const int g  = lane >> 2;
    const int tg = lane & 3;
    #pragma unroll
    for (int mt = 0; mt < 4; mt++) {
        #pragma unroll
        for (int nt = 0; nt < 4; nt++) {
            int n = n0 + n_warp + nt * 8 + tg * 2;
            float b0 = __ldg(bias + n);
            float b1 = __ldg(bias + n + 1);
            #pragma unroll
            for (int half = 0; half < 2; half++) {
                int m = m0 + m_warp + mt * 16 + g + half * 8;
                float2 v;
                v.x = acc[mt][nt][half * 2 + 0] + b0;
                v.y = acc[mt][nt][half * 2 + 1] + b1;
                *reinterpret_cast<float2*>(Cout + (size_t)m * DOUT + n) = v;
            }
        }
    }
}

// ---------------- host launcher ----------------
extern "C" void kernel_launch(void* const* d_in, const int* in_sizes, int n_in,
                              void* d_out, int out_size) {
    (void)in_sizes; (void)n_in; (void)out_size;
    const float* x         = (const float*)d_in[0];
    const float* base_w    = (const float*)d_in[1];
    const float* base_b    = (const float*)d_in[2];
    const float* shared_w1 = (const float*)d_in[3];
    const float* shared_w2 = (const float*)d_in[4];
    const float* routed_w1 = (const float*)d_in[5];
    const float* routed_w2 = (const float*)d_in[6];
    const float* router_w  = (const float*)d_in[7];
    const float* router_b  = (const float*)d_in[8];

    const int SMEM1 = 98304;   // 2 stages x 48KB
    const int SMEM2 = 147456;  // 3 stages x 48KB
    cudaFuncSetAttribute(gemm1_k, cudaFuncAttributeMaxDynamicSharedMemorySize, SMEM1);
    cudaFuncSetAttribute(gemm2_k, cudaFuncAttributeMaxDynamicSharedMemorySize, SMEM2);

    prep_B<<<dim3(KK / 32, DOUT / 32), dim3(32, 8)>>>(base_w, shared_w2, routed_w2);
    prep_W1<<<(HC * DIN + 255) / 256, 256>>>(shared_w1, routed_w1, router_w);
    split_x<<<(TT * DIN + 255) / 256, 256>>>(x);
    // GEMM1: H = A[:, :1280] @ W1cat, split-K=2 (blockIdx.x = half)
    gemm1_k<<<dim3(2, TT / 128), 256, SMEM1>>>();
    gate_kernel<<<(TT + 255) / 256, 256>>>(router_b);
    // GEMM2: out = Ah @ Bcat + bias  (1-term fp16)
    gemm2_k<<<dim3(DOUT / 128, TT / 256), 512, SMEM2>>>(base_b, (float*)d_out);
}

// round 7
// speedup vs baseline: 1.0595x; 1.0595x over previous
#include <cuda_runtime.h>
#include <cuda_fp16.h>
#include <cstdint>
#include <cstddef>

// ---------------- problem constants ----------------
#define TT   16384      // tokens = 4*4096
#define DIN  1280
#define DOUT 3840
#define KK   1408       // 1280 (x) + 16 (shared) + 96 (routed) + 16 pad
#define HC   128        // H columns: 16 shared | 96 routed | 6 router | 10 pad

// ---------------- device scratch (no cudaMalloc allowed) ----------------
__device__ __align__(256) __half g_Ah[(size_t)TT * KK];
__device__ __align__(256) __half g_Al[(size_t)TT * KK];
__device__ __align__(256) __half g_B [(size_t)DOUT * KK];
__device__ __align__(256) __half g_W1[HC * DIN];
__device__ __align__(256) float  g_H1[(size_t)TT * HC];
__device__ __align__(256) float  g_H2[(size_t)TT * HC];

// ---------------- helpers ----------------
__device__ __forceinline__ uint32_t s2u(const void* p) {
    return (uint32_t)__cvta_generic_to_shared(p);
}
__device__ __forceinline__ uint32_t swz(uint32_t o) { return o ^ ((o >> 3) & 0x70); }

__device__ __forceinline__ void cpa16(uint32_t dst, const void* src) {
    asm volatile("cp.async.cg.shared.global [%0], [%1], 16;\n" :: "r"(dst), "l"(src) : "memory");
}
__device__ __forceinline__ void cp_commit() {
    asm volatile("cp.async.commit_group;\n" ::: "memory");
}

__device__ __forceinline__ void ldsm4(uint32_t* r, uint32_t addr) {
    asm volatile("ldmatrix.sync.aligned.m8n8.x4.shared.b16 {%0,%1,%2,%3}, [%4];"
                 : "=r"(r[0]), "=r"(r[1]), "=r"(r[2]), "=r"(r[3]) : "r"(addr));
}

__device__ __forceinline__ void mma16816(float* c, const uint32_t* a, uint32_t b0, uint32_t b1) {
    asm volatile(
        "mma.sync.aligned.m16n8k16.row.col.f32.f16.f16.f32 "
        "{%0,%1,%2,%3}, {%4,%5,%6,%7}, {%8,%9}, {%0,%1,%2,%3};"
        : "+f"(c[0]), "+f"(c[1]), "+f"(c[2]), "+f"(c[3])
        : "r"(a[0]), "r"(a[1]), "r"(a[2]), "r"(a[3]), "r"(b0), "r"(b1));
}

__device__ __forceinline__ void split2(float v, __half& h, __half& l) {
    h = __float2half(v);
    l = __float2half(v - __half2float(h));
}

// ---------------- prep kernels ----------------
__global__ void prep_B(const float* __restrict__ base_w,
                       const float* __restrict__ sw2,
                       const float* __restrict__ rw2) {
    __shared__ float tile[32][33];
    const int kt = blockIdx.x * 32;
    const int nt = blockIdx.y * 32;
    const int tx = threadIdx.x, ty = threadIdx.y;  // (32, 8)
    #pragma unroll
    for (int j = 0; j < 4; j++) {
        int k = kt + ty + j * 8;
        int n = nt + tx;
        float v;
        if (k < 1280)       v = base_w[(size_t)k * DOUT + n];
        else if (k < 1296)  v = sw2[(size_t)(k - 1280) * DOUT + n];
        else if (k < 1392)  v = rw2[(size_t)(k - 1296) * DOUT + n];
        else                v = 0.f;
        tile[ty + j * 8][tx] = v;
    }
    __syncthreads();
    #pragma unroll
    for (int j = 0; j < 4; j++) {
        int n = nt + ty + j * 8;
        int k = kt + tx;
        g_B[(size_t)n * KK + k] = __float2half(tile[tx][ty + j * 8]);
    }
}

__global__ void prep_W1(const float* __restrict__ sw1,
                        const float* __restrict__ rw1,
                        const float* __restrict__ rtw) {
    int idx = blockIdx.x * blockDim.x + threadIdx.x;
    if (idx >= HC * DIN) return;
    int n = idx / DIN;
    int k = idx - n * DIN;
    float v;
    if (n < 16)        v = sw1[(size_t)k * 16 + n];
    else if (n < 112)  { int jr = n - 16; int e = jr >> 4; int r = jr & 15;
                         v = rw1[((size_t)e * DIN + k) * 16 + r]; }
    else if (n < 118)  v = rtw[(size_t)k * 6 + (n - 112)];
    else               v = 0.f;
    g_W1[idx] = __float2half(v);
}

__global__ void split_x(const float* __restrict__ x) {
    int idx = blockIdx.x * blockDim.x + threadIdx.x;
    if (idx >= TT * DIN) return;
    int t = idx / DIN;
    int k = idx - t * DIN;
    __half h, l; split2(x[idx], h, l);
    size_t o = (size_t)t * KK + k;
    g_Ah[o] = h; g_Al[o] = l;
}

__global__ void gate_kernel(const float* __restrict__ router_b) {
    int t = blockIdx.x * blockDim.x + threadIdx.x;
    if (t >= TT) return;
    const float* h1 = g_H1 + (size_t)t * HC;
    const float* h2 = g_H2 + (size_t)t * HC;
    float h[118];
    #pragma unroll
    for (int j = 0; j < 118; j++) h[j] = h1[j] + h2[j];
    float gates[6];
    float mx = -1e30f;
    #pragma unroll
    for (int e = 0; e < 6; e++) { gates[e] = h[112 + e] + router_b[e]; mx = fmaxf(mx, gates[e]); }
    float s = 0.f;
    #pragma unroll
    for (int e = 0; e < 6; e++) { gates[e] = expf(gates[e] - mx); s += gates[e]; }
    float inv = 1.f / s;
    #pragma unroll
    for (int e = 0; e < 6; e++) gates[e] *= inv;
    float cw[6] = {0.f, 0.f, 0.f, 0.f, 0.f, 0.f};
    bool used[6] = {false, false, false, false, false, false};
    for (int k = 0; k < 3; k++) {
        int bi = 0; float bv = -1.f;
        #pragma unroll
        for (int e = 0; e < 6; e++)
            if (!used[e] && gates[e] > bv) { bv = gates[e]; bi = e; }
        used[bi] = true; cw[bi] = bv;
    }
    size_t base = (size_t)t * KK + 1280;
    #pragma unroll
    for (int j = 0; j < 16; j++)
        g_Ah[base + j] = __float2half(h[j]);
    #pragma unroll
    for (int e = 0; e < 6; e++) {
        float w = cw[e];
        #pragma unroll
        for (int r = 0; r < 16; r++)
            g_Ah[base + 16 + e * 16 + r] = __float2half(w * h[16 + e * 16 + r]);
    }
    #pragma unroll
    for (int j = 112; j < 128; j++)
        g_Ah[base + j] = __float2half(0.f);
}

// ---------------- GEMM1: fp16x2 (Ah+Al) @ W1, split-K=2 ----------------
// BM=128, BN=128, BK=64, KT=10 per half. blockIdx.x = K-half.
__global__ __launch_bounds__(256, 2)
void gemm1_k() {
    constexpr int KT = 10;
    extern __shared__ __align__(1024) char smem[];
    const uint32_t sb = s2u(smem);
    const int tid = threadIdx.x;
    const int wid = tid >> 5;
    const int lane = tid & 31;
    const int m0 = blockIdx.y * 128;
    const int kbase = blockIdx.x * 640;
    float* Hout = blockIdx.x ? g_H2 : g_H1;

    const int wr = wid >> 2;
    const int wc = wid & 3;
    const int m_warp = wr * 64;
    const int n_warp = wc * 32;
    const int lm_row = lane & 15;
    const int lm_kg  = lane >> 4;

    auto load_tile = [&](int s, int it) {
        const int k0 = kbase + it * 64;
        const uint32_t st = sb + (uint32_t)s * 49152u;
        #pragma unroll
        for (int r = 0; r < 4; r++) {
            int c = tid + r * 256;
            int row = c >> 3, ch = c & 7;
            uint32_t d = swz((uint32_t)(row * 128 + ch * 16));
            size_t go = (size_t)(m0 + row) * KK + k0 + ch * 8;
            cpa16(st + d,          g_Ah + go);
            cpa16(st + 16384 + d,  g_Al + go);
        }
        #pragma unroll
        for (int r = 0; r < 4; r++) {
            int c = tid + r * 256;
            int row = c >> 3, ch = c & 7;
            uint32_t d = swz((uint32_t)(row * 128 + ch * 16));
            size_t go = (size_t)row * DIN + k0 + ch * 8;
            cpa16(st + 32768 + d,  g_W1 + go);
        }
        cp_commit();
    };

    float acc[4][4][4];
    #pragma unroll
    for (int a = 0; a < 4; a++)
        #pragma unroll
        for (int b = 0; b < 4; b++)
            #pragma unroll
            for (int c = 0; c < 4; c++) acc[a][b][c] = 0.f;

    load_tile(0, 0);

    for (int i = 0; i < KT; i++) {
        const int buf = i & 1;
        if (i + 1 < KT) {
            load_tile(buf ^ 1, i + 1);
            asm volatile("cp.async.wait_group 1;" ::: "memory");
        } else {
            asm volatile("cp.async.wait_group 0;" ::: "memory");
        }
        __syncthreads();

        const uint32_t st = sb + (uint32_t)buf * 49152u;
        #pragma unroll
        for (int ks = 0; ks < 4; ks++) {
            const int kg = ks * 2 + lm_kg;
            uint32_t bb[2][4];
            #pragma unroll
            for (int nh = 0; nh < 2; nh++) {
                uint32_t off = swz((uint32_t)((n_warp + nh * 16 + lm_row) * 128 + kg * 16));
                ldsm4(bb[nh], st + 32768 + off);
            }
            #pragma unroll
            for (int mh = 0; mh < 2; mh++) {
                uint32_t ah[2][4], al[2][4];
                #pragma unroll
                for (int q = 0; q < 2; q++) {
                    int mt = mh * 2 + q;
                    uint32_t off = swz((uint32_t)((m_warp + mt * 16 + lm_row) * 128 + kg * 16));
                    ldsm4(ah[q], st + off);
                    ldsm4(al[q], st + 16384 + off);
                }
                #pragma unroll
                for (int q = 0; q < 2; q++)
                    #pragma unroll
                    for (int nt = 0; nt < 4; nt++) {
                        const int nh = nt >> 1, sub = nt & 1;
                        mma16816(acc[mh * 2 + q][nt], ah[q], bb[nh][sub], bb[nh][sub + 2]);
                    }
                #pragma unroll
                for (int q = 0; q < 2; q++)
                    #pragma unroll
                    for (int nt = 0; nt < 4; nt++) {
                        const int nh = nt >> 1, sub = nt & 1;
                        mma16816(acc[mh * 2 + q][nt], al[q], bb[nh][sub], bb[nh][sub + 2]);
                    }
            }
        }
        __syncthreads();
    }

    const int g  = lane >> 2;
    const int tg = lane & 3;
    #pragma unroll
    for (int mt = 0; mt < 4; mt++) {
        #pragma unroll
        for (int nt = 0; nt < 4; nt++) {
            int n = n_warp + nt * 8 + tg * 2;
            #pragma unroll
            for (int half = 0; half < 2; half++) {
                int m = m0 + m_warp + mt * 16 + g + half * 8;
                float2 v;
                v.x = acc[mt][nt][half * 2 + 0];
                v.y = acc[mt][nt][half * 2 + 1];
                *reinterpret_cast<float2*>(Hout + (size_t)m * HC + n) = v;
            }
        }
    }
}

// ---------------- GEMM2: 1-term fp16, BM=128, BN=128, BK=64, 3-stage ----------------
// 256 threads, 2 CTAs/SM. Stage: Ah @0 (16KB), B @16K (16KB); stride 32K, 3 stages.
// Register fragment double-buffering across the 4 k16 steps.
// 1D grid with panel swizzle: GROUP=8 m-tiles x all 30 n-tiles per panel.
#define NT2 (DOUT / 128)   // 30
#define MT2 (TT / 128)     // 128
#define GROUP 8
__global__ __launch_bounds__(256, 2)
void gemm2_k(const float* __restrict__ bias, float* __restrict__ Cout) {
    constexpr int KT = 22;
    extern __shared__ __align__(1024) char smem[];
    const uint32_t sb = s2u(smem);
    const int tid = threadIdx.x;
    const int wid = tid >> 5;
    const int lane = tid & 31;

    const int pid = blockIdx.x;
    const int g_  = pid / (GROUP * NT2);
    const int r_  = pid % (GROUP * NT2);
    const int m0 = (g_ * GROUP + (r_ % GROUP)) * 128;
    const int n0 = (r_ / GROUP) * 128;

    const int wr = wid >> 2;
    const int wc = wid & 3;
    const int m_warp = wr * 64;
    const int n_warp = wc * 32;
    const int lm_row = lane & 15;
    const int lm_kg  = lane >> 4;

    auto load_tile = [&](int s, int it) {
        const int k0 = it * 64;
        const uint32_t st = sb + (uint32_t)s * 32768u;
        #pragma unroll
        for (int r = 0; r < 4; r++) {
            int c = tid + r * 256;
            int row = c >> 3, ch = c & 7;
            uint32_t d = swz((uint32_t)(row * 128 + ch * 16));
            cpa16(st + d,          g_Ah + (size_t)(m0 + row) * KK + k0 + ch * 8);
            cpa16(st + 16384 + d,  g_B  + (size_t)(n0 + row) * KK + k0 + ch * 8);
        }
        cp_commit();
    };

    float acc[4][4][4];
    #pragma unroll
    for (int a = 0; a < 4; a++)
        #pragma unroll
        for (int b = 0; b < 4; b++)
            #pragma unroll
            for (int c = 0; c < 4; c++) acc[a][b][c] = 0.f;

    uint32_t fa[2][4][4], fb[2][2][4];

    auto ld_frags = [&](uint32_t st, int ks, int buf) {
        const int kg = ks * 2 + lm_kg;
        #pragma unroll
        for (int nh = 0; nh < 2; nh++) {
            uint32_t off = swz((uint32_t)((n_warp + nh * 16 + lm_row) * 128 + kg * 16));
            ldsm4(fb[buf][nh], st + 16384 + off);
        }
        #pragma unroll
        for (int mt = 0; mt < 4; mt++) {
            uint32_t off = swz((uint32_t)((m_warp + mt * 16 + lm_row) * 128 + kg * 16));
            ldsm4(fa[buf][mt], st + off);
        }
    };

    load_tile(0, 0);
    load_tile(1, 1);

    for (int i = 0; i < KT; i++) {
        const int buf = i % 3;
        if (i + 2 < KT) {
            load_tile((i + 2) % 3, i + 2);
            asm volatile("cp.async.wait_group 2;" ::: "memory");
        } else if (i + 1 < KT) {
            asm volatile("cp.async.wait_group 1;" ::: "memory");
        } else {
            asm volatile("cp.async.wait_group 0;" ::: "memory");
        }
        __syncthreads();

        const uint32_t st = sb + (uint32_t)buf * 32768u;
        ld_frags(st, 0, 0);
        #pragma unroll
        for (int ks = 0; ks < 4; ks++) {
            const int cur = ks & 1;
            if (ks < 3) ld_frags(st, ks + 1, cur ^ 1);
            #pragma unroll
            for (int mt = 0; mt < 4; mt++)
                #pragma unroll
                for (int nt = 0; nt < 4; nt++) {
                    const int nh = nt >> 1, sub = nt & 1;
                    mma16816(acc[mt][nt], fa[cur][mt], fb[cur][nh][sub], fb[cur][nh][sub + 2]);
                }
        }
        __syncthreads();
    }

    const int g  = lane >> 2;
    const int tg = lane & 3;
    #pragma unroll
    for (int mt = 0; mt < 4; mt++) {
        #pragma unroll
        for (int nt = 0; nt < 4; nt++) {
            int n = n0 + n_warp + nt * 8 + tg * 2;
            float b0 = __ldg(bias + n);
            float b1 = __ldg(bias + n + 1);
            #pragma unroll
            for (int half = 0; half < 2; half++) {
                int m = m0 + m_warp + mt * 16 + g + half * 8;
                float2 v;
                v.x = acc[mt][nt][half * 2 + 0] + b0;
                v.y = acc[mt][nt][half * 2 + 1] + b1;
                *reinterpret_cast<float2*>(Cout + (size_t)m * DOUT + n) = v;
            }
        }
    }
}

// ---------------- host launcher ----------------
extern "C" void kernel_launch(void* const* d_in, const int* in_sizes, int n_in,
                              void* d_out, int out_size) {
    (void)in_sizes; (void)n_in; (void)out_size;
    const float* x         = (const float*)d_in[0];
    const float* base_w    = (const float*)d_in[1];
    const float* base_b    = (const float*)d_in[2];
    const float* shared_w1 = (const float*)d_in[3];
    const float* shared_w2 = (const float*)d_in[4];
    const float* routed_w1 = (const float*)d_in[5];
    const float* routed_w2 = (const float*)d_in[6];
    const float* router_w  = (const float*)d_in[7];
    const float* router_b  = (const float*)d_in[8];

    const int SMEM1 = 98304;  // 2 stages x 48KB
    const int SMEM2 = 98304;  // 3 stages x 32KB
    cudaFuncSetAttribute(gemm1_k, cudaFuncAttributeMaxDynamicSharedMemorySize, SMEM1);
    cudaFuncSetAttribute(gemm2_k, cudaFuncAttributeMaxDynamicSharedMemorySize, SMEM2);

    prep_B<<<dim3(KK / 32, DOUT / 32), dim3(32, 8)>>>(base_w, shared_w2, routed_w2);
    prep_W1<<<(HC * DIN + 255) / 256, 256>>>(shared_w1, routed_w1, router_w);
    split_x<<<(TT * DIN + 255) / 256, 256>>>(x);
    gemm1_k<<<dim3(2, TT / 128), 256, SMEM1>>>();
    gate_kernel<<<(TT + 255) / 256, 256>>>(router_b);
    gemm2_k<<<NT2 * MT2, 256, SMEM2>>>(base_b, (float*)d_out);
}

// round 8
// speedup vs baseline: 1.2114x; 1.1434x over previous
#include <cuda_runtime.h>
#include <cuda_fp16.h>
#include <cstdint>
#include <cstddef>

// ---------------- problem constants ----------------
#define TT   16384
#define DIN  1280
#define DOUT 3840
#define KK   1408       // 1280 (x) + 16 (shared) + 96 (routed) + 16 pad
#define HC   128
#define KT2  22         // KK/64
#define KTW  20         // DIN/64

// ---------------- device scratch: TILE-MAJOR, PRE-SWIZZLED ----------------
// A tiles: (mt in [0,128), kt in [0,22)) -> 128x64 halves, 16KB, SW128-swizzled.
__device__ __align__(1024) __half g_Ah[(size_t)128 * KT2 * 8192];
__device__ __align__(1024) __half g_Al[(size_t)128 * KT2 * 8192];
// B tiles: (nt in [0,30), kt in [0,22))
__device__ __align__(1024) __half g_B [(size_t)30 * KT2 * 8192];
// W1 tiles: (kt in [0,20))
__device__ __align__(1024) __half g_W1[(size_t)KTW * 8192];
__device__ __align__(256) float  g_H1[(size_t)TT * HC];
__device__ __align__(256) float  g_H2[(size_t)TT * HC];

// ---------------- helpers ----------------
__device__ __forceinline__ uint32_t s2u(const void* p) {
    return (uint32_t)__cvta_generic_to_shared(p);
}
__device__ __forceinline__ uint32_t swz(uint32_t o) { return o ^ ((o >> 3) & 0x70); }

__device__ __forceinline__ void mbar_init(uint32_t a, uint32_t cnt) {
    asm volatile("mbarrier.init.shared.b64 [%0], %1;" :: "r"(a), "r"(cnt) : "memory");
}
__device__ __forceinline__ void mbar_expect_tx(uint32_t a, uint32_t tx) {
    asm volatile("mbarrier.arrive.expect_tx.shared.b64 _, [%0], %1;" :: "r"(a), "r"(tx) : "memory");
}
__device__ __forceinline__ void mbar_wait(uint32_t a, uint32_t parity) {
    asm volatile(
        "{\n\t.reg .pred P;\n\t"
        "WAIT_%=:\n\t"
        "mbarrier.try_wait.parity.acquire.cta.shared::cta.b64 P, [%0], %1, 0x989680;\n\t"
        "@!P bra WAIT_%=;\n\t}"
        :: "r"(a), "r"(parity) : "memory");
}
__device__ __forceinline__ void bulk_g2s(uint32_t dst, const void* src, uint32_t bytes, uint32_t mbar) {
    asm volatile(
        "cp.async.bulk.shared::cluster.global.mbarrier::complete_tx::bytes [%0], [%1], %2, [%3];"
        :: "r"(dst), "l"(src), "r"(bytes), "r"(mbar) : "memory");
}

__device__ __forceinline__ void ldsm4(uint32_t* r, uint32_t addr) {
    asm volatile("ldmatrix.sync.aligned.m8n8.x4.shared.b16 {%0,%1,%2,%3}, [%4];"
                 : "=r"(r[0]), "=r"(r[1]), "=r"(r[2]), "=r"(r[3]) : "r"(addr));
}
__device__ __forceinline__ void mma16816(float* c, const uint32_t* a, uint32_t b0, uint32_t b1) {
    asm volatile(
        "mma.sync.aligned.m16n8k16.row.col.f32.f16.f16.f32 "
        "{%0,%1,%2,%3}, {%4,%5,%6,%7}, {%8,%9}, {%0,%1,%2,%3};"
        : "+f"(c[0]), "+f"(c[1]), "+f"(c[2]), "+f"(c[3])
        : "r"(a[0]), "r"(a[1]), "r"(a[2]), "r"(a[3]), "r"(b0), "r"(b1));
}
__device__ __forceinline__ void split2(float v, __half& h, __half& l) {
    h = __float2half(v);
    l = __float2half(v - __half2float(h));
}
// byte offset of half (row, col) inside a swizzled 128x64 tile
__device__ __forceinline__ uint32_t tile_addr(int row, int col) {
    return swz((uint32_t)(row * 128 + col * 2));
}

// ---------------- prep kernels ----------------
// split x into hi/lo fp16, tile-major swizzled. One 16B chunk (8 k) per thread.
__global__ void split_x(const float* __restrict__ x) {
    int idx = blockIdx.x * blockDim.x + threadIdx.x;   // TT * 160 chunks
    if (idx >= TT * (DIN / 8)) return;
    int t  = idx / (DIN / 8);
    int c8 = idx - t * (DIN / 8);
    int k  = c8 * 8;
    const float4* xp = reinterpret_cast<const float4*>(x + (size_t)t * DIN + k);
    float4 v0 = xp[0], v1 = xp[1];
    float vv[8] = {v0.x, v0.y, v0.z, v0.w, v1.x, v1.y, v1.z, v1.w};
    __half hh[8], ll[8];
    #pragma unroll
    for (int j = 0; j < 8; j++) split2(vv[j], hh[j], ll[j]);
    int mt = t >> 7, row = t & 127, kt = k >> 6, col = k & 63;
    size_t tile = ((size_t)(mt * KT2 + kt)) << 13;  // halves
    uint32_t off = tile_addr(row, col) >> 1;        // half index
    *reinterpret_cast<uint4*>(g_Ah + tile + off) = *reinterpret_cast<uint4*>(hh);
    *reinterpret_cast<uint4*>(g_Al + tile + off) = *reinterpret_cast<uint4*>(ll);
}

// B tiles: B[n,k] = cat(base_w, sw2, rw2)[k,n], fp16, swizzled tile-major.
__global__ void prep_B(const float* __restrict__ base_w,
                       const float* __restrict__ sw2,
                       const float* __restrict__ rw2) {
    __shared__ float tile[32][33];
    const int kt32 = blockIdx.x * 32;
    const int nt32 = blockIdx.y * 32;
    const int tx = threadIdx.x, ty = threadIdx.y;  // (32, 8)
    #pragma unroll
    for (int j = 0; j < 4; j++) {
        int k = kt32 + ty + j * 8;
        int n = nt32 + tx;
        float v;
        if (k < 1280)       v = base_w[(size_t)k * DOUT + n];
        else if (k < 1296)  v = sw2[(size_t)(k - 1280) * DOUT + n];
        else if (k < 1392)  v = rw2[(size_t)(k - 1296) * DOUT + n];
        else                v = 0.f;
        tile[ty + j * 8][tx] = v;
    }
    __syncthreads();
    #pragma unroll
    for (int j = 0; j < 4; j++) {
        int n = nt32 + ty + j * 8;
        int k = kt32 + tx;
        int nt = n >> 7, row = n & 127, kt = k >> 6, col = k & 63;
        size_t to = ((size_t)(nt * KT2 + kt)) << 13;
        g_B[to + (tile_addr(row, col) >> 1)] = __float2half(tile[tx][ty + j * 8]);
    }
}

__global__ void prep_W1(const float* __restrict__ sw1,
                        const float* __restrict__ rw1,
                        const float* __restrict__ rtw) {
    int idx = blockIdx.x * blockDim.x + threadIdx.x;
    if (idx >= HC * DIN) return;
    int n = idx / DIN;
    int k = idx - n * DIN;
    float v;
    if (n < 16)        v = sw1[(size_t)k * 16 + n];
    else if (n < 112)  { int jr = n - 16; int e = jr >> 4; int r = jr & 15;
                         v = rw1[((size_t)e * DIN + k) * 16 + r]; }
    else if (n < 118)  v = rtw[(size_t)k * 6 + (n - 112)];
    else               v = 0.f;
    int kt = k >> 6, col = k & 63;
    g_W1[(((size_t)kt) << 13) + (tile_addr(n, col) >> 1)] = __float2half(v);
}

__global__ void gate_kernel(const float* __restrict__ router_b) {
    int t = blockIdx.x * blockDim.x + threadIdx.x;
    if (t >= TT) return;
    const float* h1 = g_H1 + (size_t)t * HC;
    const float* h2 = g_H2 + (size_t)t * HC;
    float h[118];
    #pragma unroll
    for (int j = 0; j < 118; j++) h[j] = h1[j] + h2[j];
    float gates[6];
    float mx = -1e30f;
    #pragma unroll
    for (int e = 0; e < 6; e++) { gates[e] = h[112 + e] + router_b[e]; mx = fmaxf(mx, gates[e]); }
    float s = 0.f;
    #pragma unroll
    for (int e = 0; e < 6; e++) { gates[e] = expf(gates[e] - mx); s += gates[e]; }
    float inv = 1.f / s;
    #pragma unroll
    for (int e = 0; e < 6; e++) gates[e] *= inv;
    float cw[6] = {0.f, 0.f, 0.f, 0.f, 0.f, 0.f};
    bool used[6] = {false, false, false, false, false, false};
    for (int k = 0; k < 3; k++) {
        int bi = 0; float bv = -1.f;
        #pragma unroll
        for (int e = 0; e < 6; e++)
            if (!used[e] && gates[e] > bv) { bv = gates[e]; bi = e; }
        used[bi] = true; cw[bi] = bv;
    }
    // g vector: 128 halves -> tiles kt 20, 21
    __half gv[128];
    #pragma unroll
    for (int j = 0; j < 16; j++) gv[j] = __float2half(h[j]);
    #pragma unroll
    for (int e = 0; e < 6; e++) {
        float w = cw[e];
        #pragma unroll
        for (int r = 0; r < 16; r++)
            gv[16 + e * 16 + r] = __float2half(w * h[16 + e * 16 + r]);
    }
    #pragma unroll
    for (int j = 112; j < 128; j++) gv[j] = __float2half(0.f);

    int mt = t >> 7, row = t & 127;
    #pragma unroll
    for (int half = 0; half < 2; half++) {
        size_t tile = ((size_t)(mt * KT2 + 20 + half)) << 13;
        #pragma unroll
        for (int c8 = 0; c8 < 8; c8++) {
            uint32_t off = tile_addr(row, c8 * 8) >> 1;
            *reinterpret_cast<uint4*>(g_Ah + tile + off) =
                *reinterpret_cast<uint4*>(gv + half * 64 + c8 * 8);
        }
    }
}

// ---------------- GEMM1: fp16x2 (Ah+Al) @ W1, split-K=2, bulk loads ----------------
// BM=128, BN=128, BK=64, KT=10 per half. Stage: Ah|Al|W1 = 48KB, 2 stages.
__global__ __launch_bounds__(256, 2)
void gemm1_k() {
    constexpr int KT = 10;
    extern __shared__ __align__(1024) char smem[];
    const uint32_t sb = s2u(smem);          // [0,64): mbars; stages at +128
    const uint32_t stage0 = sb + 128;
    const int tid = threadIdx.x;
    const int wid = tid >> 5;
    const int lane = tid & 31;
    const int mt = blockIdx.y;
    const int ktb = blockIdx.x * KT;        // tile index base in W1-space
    float* Hout = blockIdx.x ? g_H2 : g_H1;

    if (tid == 0) { mbar_init(sb, 1); mbar_init(sb + 8, 1); }
    __syncthreads();

    auto issue = [&](int it) {
        const int s = it & 1;
        const uint32_t st = stage0 + (uint32_t)s * 49152u;
        const int ktg = ktb + it;
        mbar_expect_tx(sb + s * 8, 49152);
        bulk_g2s(st,          g_Ah + (((size_t)(mt * KT2 + ktg)) << 13), 16384, sb + s * 8);
        bulk_g2s(st + 16384,  g_Al + (((size_t)(mt * KT2 + ktg)) << 13), 16384, sb + s * 8);
        bulk_g2s(st + 32768,  g_W1 + (((size_t)ktg) << 13),              16384, sb + s * 8);
    };

    const int wr = wid >> 2;
    const int wc = wid & 3;
    const int m_warp = wr * 64;
    const int n_warp = wc * 32;
    const int lm_row = lane & 15;
    const int lm_kg  = lane >> 4;

    float acc[4][4][4];
    #pragma unroll
    for (int a = 0; a < 4; a++)
        #pragma unroll
        for (int b = 0; b < 4; b++)
            #pragma unroll
            for (int c = 0; c < 4; c++) acc[a][b][c] = 0.f;

    if (tid == 0) issue(0);

    for (int i = 0; i < KT; i++) {
        __syncthreads();
        if (i + 1 < KT && tid == 0) issue(i + 1);
        mbar_wait(sb + (i & 1) * 8, (i >> 1) & 1);

        const uint32_t st = stage0 + (uint32_t)(i & 1) * 49152u;
        #pragma unroll
        for (int ks = 0; ks < 4; ks++) {
            const int kg = ks * 2 + lm_kg;
            uint32_t bb[2][4];
            #pragma unroll
            for (int nh = 0; nh < 2; nh++) {
                uint32_t off = swz((uint32_t)((n_warp + nh * 16 + lm_row) * 128 + kg * 16));
                ldsm4(bb[nh], st + 32768 + off);
            }
            #pragma unroll
            for (int mh = 0; mh < 2; mh++) {
                uint32_t ah[2][4], al[2][4];
                #pragma unroll
                for (int q = 0; q < 2; q++) {
                    int mtt = mh * 2 + q;
                    uint32_t off = swz((uint32_t)((m_warp + mtt * 16 + lm_row) * 128 + kg * 16));
                    ldsm4(ah[q], st + off);
                    ldsm4(al[q], st + 16384 + off);
                }
                #pragma unroll
                for (int q = 0; q < 2; q++)
                    #pragma unroll
                    for (int nt = 0; nt < 4; nt++) {
                        const int nh = nt >> 1, sub = nt & 1;
                        mma16816(acc[mh * 2 + q][nt], ah[q], bb[nh][sub], bb[nh][sub + 2]);
                    }
                #pragma unroll
                for (int q = 0; q < 2; q++)
                    #pragma unroll
                    for (int nt = 0; nt < 4; nt++) {
                        const int nh = nt >> 1, sub = nt & 1;
                        mma16816(acc[mh * 2 + q][nt], al[q], bb[nh][sub], bb[nh][sub + 2]);
                    }
            }
        }
    }

    const int g  = lane >> 2;
    const int tg = lane & 3;
    const int m0 = mt * 128;
    #pragma unroll
    for (int mtt = 0; mtt < 4; mtt++) {
        #pragma unroll
        for (int nt = 0; nt < 4; nt++) {
            int n = n_warp + nt * 8 + tg * 2;
            #pragma unroll
            for (int half = 0; half < 2; half++) {
                int m = m0 + m_warp + mtt * 16 + g + half * 8;
                float2 v;
                v.x = acc[mtt][nt][half * 2 + 0];
                v.y = acc[mtt][nt][half * 2 + 1];
                *reinterpret_cast<float2*>(Hout + (size_t)m * HC + n) = v;
            }
        }
    }
}

// ---------------- GEMM2: 1-term fp16, BM=BN=128, BK=64, 3-stage bulk pipeline ----------------
#define NT2 (DOUT / 128)   // 30
#define MT2 (TT / 128)     // 128
#define GROUP 8
__global__ __launch_bounds__(256, 2)
void gemm2_k(const float* __restrict__ bias, float* __restrict__ Cout) {
    constexpr int KT = KT2;
    extern __shared__ __align__(1024) char smem[];
    const uint32_t sb = s2u(smem);
    const uint32_t stage0 = sb + 128;
    const int tid = threadIdx.x;
    const int wid = tid >> 5;
    const int lane = tid & 31;

    const int pid = blockIdx.x;
    const int g_  = pid / (GROUP * NT2);
    const int r_  = pid % (GROUP * NT2);
    const int mt = g_ * GROUP + (r_ % GROUP);
    const int nt0 = r_ / GROUP;
    const int m0 = mt * 128;
    const int n0 = nt0 * 128;

    if (tid == 0) { mbar_init(sb, 1); mbar_init(sb + 8, 1); mbar_init(sb + 16, 1); }
    __syncthreads();

    auto issue = [&](int it) {
        const int s = it % 3;
        const uint32_t st = stage0 + (uint32_t)s * 32768u;
        mbar_expect_tx(sb + s * 8, 32768);
        bulk_g2s(st,          g_Ah + (((size_t)(mt  * KT2 + it)) << 13), 16384, sb + s * 8);
        bulk_g2s(st + 16384,  g_B  + (((size_t)(nt0 * KT2 + it)) << 13), 16384, sb + s * 8);
    };

    const int wr = wid >> 2;
    const int wc = wid & 3;
    const int m_warp = wr * 64;
    const int n_warp = wc * 32;
    const int lm_row = lane & 15;
    const int lm_kg  = lane >> 4;

    float acc[4][4][4];
    #pragma unroll
    for (int a = 0; a < 4; a++)
        #pragma unroll
        for (int b = 0; b < 4; b++)
            #pragma unroll
            for (int c = 0; c < 4; c++) acc[a][b][c] = 0.f;

    uint32_t fa[2][4][4], fb[2][2][4];
    auto ld_frags = [&](uint32_t st, int ks, int buf) {
        const int kg = ks * 2 + lm_kg;
        #pragma unroll
        for (int nh = 0; nh < 2; nh++) {
            uint32_t off = swz((uint32_t)((n_warp + nh * 16 + lm_row) * 128 + kg * 16));
            ldsm4(fb[buf][nh], st + 16384 + off);
        }
        #pragma unroll
        for (int mtt = 0; mtt < 4; mtt++) {
            uint32_t off = swz((uint32_t)((m_warp + mtt * 16 + lm_row) * 128 + kg * 16));
            ldsm4(fa[buf][mtt], st + off);
        }
    };

    if (tid == 0) { issue(0); issue(1); }

    for (int i = 0; i < KT; i++) {
        __syncthreads();
        if (i + 2 < KT && tid == 0) issue(i + 2);
        mbar_wait(sb + (i % 3) * 8, (i / 3) & 1);

        const uint32_t st = stage0 + (uint32_t)(i % 3) * 32768u;
        ld_frags(st, 0, 0);
        #pragma unroll
        for (int ks = 0; ks < 4; ks++) {
            const int cur = ks & 1;
            if (ks < 3) ld_frags(st, ks + 1, cur ^ 1);
            #pragma unroll
            for (int mtt = 0; mtt < 4; mtt++)
                #pragma unroll
                for (int nt = 0; nt < 4; nt++) {
                    const int nh = nt >> 1, sub = nt & 1;
                    mma16816(acc[mtt][nt], fa[cur][mtt], fb[cur][nh][sub], fb[cur][nh][sub + 2]);
                }
        }
    }

    const int g  = lane >> 2;
    const int tg = lane & 3;
    #pragma unroll
    for (int mtt = 0; mtt < 4; mtt++) {
        #pragma unroll
        for (int nt = 0; nt < 4; nt++) {
            int n = n0 + n_warp + nt * 8 + tg * 2;
            float b0 = __ldg(bias + n);
            float b1 = __ldg(bias + n + 1);
            #pragma unroll
            for (int half = 0; half < 2; half++) {
                int m = m0 + m_warp + mtt * 16 + g + half * 8;
                float2 v;
                v.x = acc[mtt][nt][half * 2 + 0] + b0;
                v.y = acc[mtt][nt][half * 2 + 1] + b1;
                *reinterpret_cast<float2*>(Cout + (size_t)m * DOUT + n) = v;
            }
        }
    }
}

// ---------------- host launcher ----------------
extern "C" void kernel_launch(void* const* d_in, const int* in_sizes, int n_in,
                              void* d_out, int out_size) {
    (void)in_sizes; (void)n_in; (void)out_size;
    const float* x         = (const float*)d_in[0];
    const float* base_w    = (const float*)d_in[1];
    const float* base_b    = (const float*)d_in[2];
    const float* shared_w1 = (const float*)d_in[3];
    const float* shared_w2 = (const float*)d_in[4];
    const float* routed_w1 = (const float*)d_in[5];
    const float* routed_w2 = (const float*)d_in[6];
    const float* router_w  = (const float*)d_in[7];
    const float* router_b  = (const float*)d_in[8];

    const int SMEM1 = 128 + 2 * 49152;   // 98432
    const int SMEM2 = 128 + 3 * 32768;   // 98432
    cudaFuncSetAttribute(gemm1_k, cudaFuncAttributeMaxDynamicSharedMemorySize, SMEM1);
    cudaFuncSetAttribute(gemm2_k, cudaFuncAttributeMaxDynamicSharedMemorySize, SMEM2);

    prep_B<<<dim3(KK / 32, DOUT / 32), dim3(32, 8)>>>(base_w, shared_w2, routed_w2);
    prep_W1<<<(HC * DIN + 255) / 256, 256>>>(shared_w1, routed_w1, router_w);
    split_x<<<(TT * (DIN / 8) + 255) / 256, 256>>>(x);
    gemm1_k<<<dim3(2, TT / 128), 256, SMEM1>>>();
    gate_kernel<<<(TT + 255) / 256, 256>>>(router_b);
    gemm2_k<<<NT2 * MT2, 256, SMEM2>>>(base_b, (float*)d_out);
}

// round 9
// speedup vs baseline: 1.2476x; 1.0299x over previous
#include <cuda_runtime.h>
#include <cuda_fp16.h>
#include <cstdint>
#include <cstddef>

// ---------------- problem constants ----------------
#define TT   16384
#define DIN  1280
#define DOUT 3840
#define KK   1408       // 1280 (x) + 128 (g: shared|routed|pad)
#define HC   128
#define KT2  22         // KK/64
#define KTW  20         // DIN/64
#define NT2  (DOUT / 128)   // 30
#define MT2  (TT / 128)     // 128
#define GROUP 8

// ---------------- device scratch: TILE-MAJOR, PRE-SWIZZLED ----------------
__device__ __align__(1024) __half g_Ah[(size_t)MT2 * KT2 * 8192];
__device__ __align__(1024) __half g_B [(size_t)NT2 * KT2 * 8192];
__device__ __align__(1024) __half g_W1[(size_t)KTW * 8192];
__device__ __align__(256) float  g_H1[(size_t)TT * HC];
__device__ __align__(256) float  g_H2[(size_t)TT * HC];

// ---------------- helpers ----------------
__device__ __forceinline__ uint32_t s2u(const void* p) {
    return (uint32_t)__cvta_generic_to_shared(p);
}
__device__ __forceinline__ uint32_t swz(uint32_t o) { return o ^ ((o >> 3) & 0x70); }

__device__ __forceinline__ void mbar_init(uint32_t a, uint32_t cnt) {
    asm volatile("mbarrier.init.shared.b64 [%0], %1;" :: "r"(a), "r"(cnt) : "memory");
}
__device__ __forceinline__ void mbar_expect_tx(uint32_t a, uint32_t tx) {
    asm volatile("mbarrier.arrive.expect_tx.shared.b64 _, [%0], %1;" :: "r"(a), "r"(tx) : "memory");
}
__device__ __forceinline__ void mbar_arrive(uint32_t a) {
    asm volatile("mbarrier.arrive.shared.b64 _, [%0];" :: "r"(a) : "memory");
}
__device__ __forceinline__ void mbar_wait(uint32_t a, uint32_t parity) {
    asm volatile(
        "{\n\t.reg .pred P;\n\t"
        "WAIT_%=:\n\t"
        "mbarrier.try_wait.parity.acquire.cta.shared::cta.b64 P, [%0], %1, 0x989680;\n\t"
        "@!P bra WAIT_%=;\n\t}"
        :: "r"(a), "r"(parity) : "memory");
}
__device__ __forceinline__ void bulk_g2s(uint32_t dst, const void* src, uint32_t bytes, uint32_t mbar) {
    asm volatile(
        "cp.async.bulk.shared::cluster.global.mbarrier::complete_tx::bytes [%0], [%1], %2, [%3];"
        :: "r"(dst), "l"(src), "r"(bytes), "r"(mbar) : "memory");
}
__device__ __forceinline__ void ldsm4(uint32_t* r, uint32_t addr) {
    asm volatile("ldmatrix.sync.aligned.m8n8.x4.shared.b16 {%0,%1,%2,%3}, [%4];"
                 : "=r"(r[0]), "=r"(r[1]), "=r"(r[2]), "=r"(r[3]) : "r"(addr));
}
__device__ __forceinline__ void mma16816(float* c, const uint32_t* a, uint32_t b0, uint32_t b1) {
    asm volatile(
        "mma.sync.aligned.m16n8k16.row.col.f32.f16.f16.f32 "
        "{%0,%1,%2,%3}, {%4,%5,%6,%7}, {%8,%9}, {%0,%1,%2,%3};"
        : "+f"(c[0]), "+f"(c[1]), "+f"(c[2]), "+f"(c[3])
        : "r"(a[0]), "r"(a[1]), "r"(a[2]), "r"(a[3]), "r"(b0), "r"(b1));
}
__device__ __forceinline__ uint32_t tile_addr(int row, int col) {
    return swz((uint32_t)(row * 128 + col * 2));
}

// ---------------- prep kernels ----------------
__global__ void split_x(const float* __restrict__ x) {
    int idx = blockIdx.x * blockDim.x + threadIdx.x;   // TT * 160 chunks
    if (idx >= TT * (DIN / 8)) return;
    int t  = idx / (DIN / 8);
    int c8 = idx - t * (DIN / 8);
    int k  = c8 * 8;
    const float4* xp = reinterpret_cast<const float4*>(x + (size_t)t * DIN + k);
    float4 v0 = xp[0], v1 = xp[1];
    float vv[8] = {v0.x, v0.y, v0.z, v0.w, v1.x, v1.y, v1.z, v1.w};
    __half hh[8];
    #pragma unroll
    for (int j = 0; j < 8; j++) hh[j] = __float2half(vv[j]);
    int mt = t >> 7, row = t & 127, kt = k >> 6, col = k & 63;
    size_t tile = ((size_t)(mt * KT2 + kt)) << 13;
    uint32_t off = tile_addr(row, col) >> 1;
    *reinterpret_cast<uint4*>(g_Ah + tile + off) = *reinterpret_cast<uint4*>(hh);
}

__global__ void prep_B(const float* __restrict__ base_w,
                       const float* __restrict__ sw2,
                       const float* __restrict__ rw2) {
    __shared__ float tile[32][33];
    const int kt32 = blockIdx.x * 32;
    const int nt32 = blockIdx.y * 32;
    const int tx = threadIdx.x, ty = threadIdx.y;  // (32, 8)
    #pragma unroll
    for (int j = 0; j < 4; j++) {
        int k = kt32 + ty + j * 8;
        int n = nt32 + tx;
        float v;
        if (k < 1280)       v = base_w[(size_t)k * DOUT + n];
        else if (k < 1296)  v = sw2[(size_t)(k - 1280) * DOUT + n];
        else if (k < 1392)  v = rw2[(size_t)(k - 1296) * DOUT + n];
        else                v = 0.f;
        tile[ty + j * 8][tx] = v;
    }
    __syncthreads();
    #pragma unroll
    for (int j = 0; j < 4; j++) {
        int n = nt32 + ty + j * 8;
        int k = kt32 + tx;
        int nt = n >> 7, row = n & 127, kt = k >> 6, col = k & 63;
        size_t to = ((size_t)(nt * KT2 + kt)) << 13;
        g_B[to + (tile_addr(row, col) >> 1)] = __float2half(tile[tx][ty + j * 8]);
    }
}

__global__ void prep_W1(const float* __restrict__ sw1,
                        const float* __restrict__ rw1,
                        const float* __restrict__ rtw) {
    int idx = blockIdx.x * blockDim.x + threadIdx.x;
    if (idx >= HC * DIN) return;
    int n = idx / DIN;
    int k = idx - n * DIN;
    float v;
    if (n < 16)        v = sw1[(size_t)k * 16 + n];
    else if (n < 112)  { int jr = n - 16; int e = jr >> 4; int r = jr & 15;
                         v = rw1[((size_t)e * DIN + k) * 16 + r]; }
    else if (n < 118)  v = rtw[(size_t)k * 6 + (n - 112)];
    else               v = 0.f;
    int kt = k >> 6, col = k & 63;
    g_W1[(((size_t)kt) << 13) + (tile_addr(n, col) >> 1)] = __float2half(v);
}

__global__ void gate_kernel(const float* __restrict__ router_b) {
    int t = blockIdx.x * blockDim.x + threadIdx.x;
    if (t >= TT) return;
    const float* h1 = g_H1 + (size_t)t * HC;
    const float* h2 = g_H2 + (size_t)t * HC;
    float h[118];
    #pragma unroll
    for (int j = 0; j < 118; j++) h[j] = h1[j] + h2[j];
    float gates[6];
    float mx = -1e30f;
    #pragma unroll
    for (int e = 0; e < 6; e++) { gates[e] = h[112 + e] + router_b[e]; mx = fmaxf(mx, gates[e]); }
    float s = 0.f;
    #pragma unroll
    for (int e = 0; e < 6; e++) { gates[e] = expf(gates[e] - mx); s += gates[e]; }
    float inv = 1.f / s;
    #pragma unroll
    for (int e = 0; e < 6; e++) gates[e] *= inv;
    float cw[6] = {0.f, 0.f, 0.f, 0.f, 0.f, 0.f};
    bool used[6] = {false, false, false, false, false, false};
    for (int k = 0; k < 3; k++) {
        int bi = 0; float bv = -1.f;
        #pragma unroll
        for (int e = 0; e < 6; e++)
            if (!used[e] && gates[e] > bv) { bv = gates[e]; bi = e; }
        used[bi] = true; cw[bi] = bv;
    }
    __half gv[128];
    #pragma unroll
    for (int j = 0; j < 16; j++) gv[j] = __float2half(h[j]);
    #pragma unroll
    for (int e = 0; e < 6; e++) {
        float w = cw[e];
        #pragma unroll
        for (int r = 0; r < 16; r++)
            gv[16 + e * 16 + r] = __float2half(w * h[16 + e * 16 + r]);
    }
    #pragma unroll
    for (int j = 112; j < 128; j++) gv[j] = __float2half(0.f);

    int mt = t >> 7, row = t & 127;
    #pragma unroll
    for (int half = 0; half < 2; half++) {
        size_t tile = ((size_t)(mt * KT2 + 20 + half)) << 13;
        #pragma unroll
        for (int c8 = 0; c8 < 8; c8++) {
            uint32_t off = tile_addr(row, c8 * 8) >> 1;
            *reinterpret_cast<uint4*>(g_Ah + tile + off) =
                *reinterpret_cast<uint4*>(gv + half * 64 + c8 * 8);
        }
    }
}

// ---------------- unified 1-term fp16 GEMM ----------------
// BM=BN=128, BK=64, 256 thr (8 warps, 64x32 warp tile), 3-stage bulk pipeline
// with full/empty mbarrier flow control (no per-iteration __syncthreads).
// smem: [0,24) full mbars, [32,56) empty mbars, stages at +128 (3 x 32KB).
template <int KT, bool IS_G2>
__global__ __launch_bounds__(256, 2)
void gemm_k(const float* __restrict__ bias, float* __restrict__ Cout) {
    extern __shared__ __align__(1024) char smem[];
    const uint32_t sb = s2u(smem);
    const uint32_t stage0 = sb + 128;
    const int tid = threadIdx.x;
    const int wid = tid >> 5;
    const int lane = tid & 31;

    int mt, nt0, ktoff;
    if constexpr (IS_G2) {
        const int pid = blockIdx.x;
        const int gg = pid / (GROUP * NT2);
        const int rr = pid % (GROUP * NT2);
        mt = gg * GROUP + (rr % GROUP);
        nt0 = rr / GROUP;
        ktoff = 0;
    } else {
        mt = blockIdx.y;
        nt0 = 0;
        ktoff = blockIdx.x * KT;
    }

    if (tid == 0) {
        #pragma unroll
        for (int s = 0; s < 3; s++) {
            mbar_init(sb + s * 8, 1);        // full: tx-based
            mbar_init(sb + 32 + s * 8, 8);   // empty: 8 warp arrivals
        }
    }
    __syncthreads();

    auto issue = [&](int it) {
        const int s = it % 3;
        const uint32_t st = stage0 + (uint32_t)s * 32768u;
        mbar_expect_tx(sb + s * 8, 32768);
        bulk_g2s(st, g_Ah + (((size_t)(mt * KT2 + ktoff + it)) << 13), 16384, sb + s * 8);
        const __half* bsrc = IS_G2 ? (g_B + (((size_t)(nt0 * KT2 + it)) << 13))
                                   : (g_W1 + (((size_t)(ktoff + it)) << 13));
        bulk_g2s(st + 16384, bsrc, 16384, sb + s * 8);
    };

    const int wr = wid >> 2;
    const int wc = wid & 3;
    const int m_warp = wr * 64;
    const int n_warp = wc * 32;
    const int lm_row = lane & 15;
    const int lm_kg  = lane >> 4;

    float acc[4][4][4];
    #pragma unroll
    for (int a = 0; a < 4; a++)
        #pragma unroll
        for (int b = 0; b < 4; b++)
            #pragma unroll
            for (int c = 0; c < 4; c++) acc[a][b][c] = 0.f;

    uint32_t fa[2][4][4], fb[2][2][4];
    auto ld_frags = [&](uint32_t st, int ks, int buf) {
        const int kg = ks * 2 + lm_kg;
        #pragma unroll
        for (int nh = 0; nh < 2; nh++) {
            uint32_t off = swz((uint32_t)((n_warp + nh * 16 + lm_row) * 128 + kg * 16));
            ldsm4(fb[buf][nh], st + 16384 + off);
        }
        #pragma unroll
        for (int mtt = 0; mtt < 4; mtt++) {
            uint32_t off = swz((uint32_t)((m_warp + mtt * 16 + lm_row) * 128 + kg * 16));
            ldsm4(fa[buf][mtt], st + off);
        }
    };

    if (tid == 0) { issue(0); issue(1); }

    for (int i = 0; i < KT; i++) {
        if (i + 2 < KT && tid == 0) {
            const int j = i + 2;
            if (j >= 3) mbar_wait(sb + 32 + (j % 3) * 8, ((j / 3) - 1) & 1);
            issue(j);
        }
        mbar_wait(sb + (i % 3) * 8, (i / 3) & 1);

        const uint32_t st = stage0 + (uint32_t)(i % 3) * 32768u;
        ld_frags(st, 0, 0);
        #pragma unroll
        for (int ks = 0; ks < 4; ks++) {
            const int cur = ks & 1;
            if (ks < 3) ld_frags(st, ks + 1, cur ^ 1);
            #pragma unroll
            for (int mtt = 0; mtt < 4; mtt++)
                #pragma unroll
                for (int nt = 0; nt < 4; nt++) {
                    const int nh = nt >> 1, sub = nt & 1;
                    mma16816(acc[mtt][nt], fa[cur][mtt], fb[cur][nh][sub], fb[cur][nh][sub + 2]);
                }
        }
        if (lane == 0) mbar_arrive(sb + 32 + (i % 3) * 8);
    }

    const int g  = lane >> 2;
    const int tg = lane & 3;
    const int m0 = mt * 128;
    const int n0 = nt0 * 128;
    float* Hout = nullptr;
    if constexpr (!IS_G2) Hout = blockIdx.x ? g_H2 : g_H1;
    #pragma unroll
    for (int mtt = 0; mtt < 4; mtt++) {
        #pragma unroll
        for (int nt = 0; nt < 4; nt++) {
            int n = n0 + n_warp + nt * 8 + tg * 2;
            float b0 = 0.f, b1 = 0.f;
            if (IS_G2) { b0 = __ldg(bias + n); b1 = __ldg(bias + n + 1); }
            #pragma unroll
            for (int half = 0; half < 2; half++) {
                int m = m0 + m_warp + mtt * 16 + g + half * 8;
                float2 v;
                v.x = acc[mtt][nt][half * 2 + 0] + b0;
                v.y = acc[mtt][nt][half * 2 + 1] + b1;
                if (IS_G2)
                    *reinterpret_cast<float2*>(Cout + (size_t)m * DOUT + n) = v;
                else
                    *reinterpret_cast<float2*>(Hout + (size_t)m * HC + (n - n0)) = v;
            }
        }
    }
}

// ---------------- host launcher ----------------
extern "C" void kernel_launch(void* const* d_in, const int* in_sizes, int n_in,
                              void* d_out, int out_size) {
    (void)in_sizes; (void)n_in; (void)out_size;
    const float* x         = (const float*)d_in[0];
    const float* base_w    = (const float*)d_in[1];
    const float* base_b    = (const float*)d_in[2];
    const float* shared_w1 = (const float*)d_in[3];
    const float* shared_w2 = (const float*)d_in[4];
    const float* routed_w1 = (const float*)d_in[5];
    const float* routed_w2 = (const float*)d_in[6];
    const float* router_w  = (const float*)d_in[7];
    const float* router_b  = (const float*)d_in[8];

    const int SMEM = 128 + 3 * 32768;   // 98432
    cudaFuncSetAttribute(gemm_k<10, false>, cudaFuncAttributeMaxDynamicSharedMemorySize, SMEM);
    cudaFuncSetAttribute(gemm_k<KT2, true>, cudaFuncAttributeMaxDynamicSharedMemorySize, SMEM);

    prep_B<<<dim3(KK / 32, DOUT / 32), dim3(32, 8)>>>(base_w, shared_w2, routed_w2);
    prep_W1<<<(HC * DIN + 255) / 256, 256>>>(shared_w1, routed_w1, router_w);
    split_x<<<(TT * (DIN / 8) + 255) / 256, 256>>>(x);
    gemm_k<10, false><<<dim3(2, MT2), 256, SMEM>>>(nullptr, nullptr);
    gate_kernel<<<(TT + 255) / 256, 256>>>(router_b);
    gemm_k<KT2, true><<<NT2 * MT2, 256, SMEM>>>(base_b, (float*)d_out);
}